// round 2
// baseline (speedup 1.0000x reference)
#include <cuda_runtime.h>

#define BB   8
#define CC   256
#define NN   2048
#define KK   16
#define OUTC 256
#define NT   32           // nodes per block in fused kernel

typedef unsigned long long u64;

// ---------------- scratch (no allocations allowed) ----------------
__device__ float g_xT[BB * NN * CC];     // x transposed: [B][N][C], 16 MB
__device__ float g_p [BB * NN];          // per-node score with a_w[:C]
__device__ float g_q [BB * NN];          // per-node score with a_w[C:]
__device__ float g_Wt[2 * CC * OUTC];    // nn_w transposed: [c2][o], 512 KB

// ---------------- packed f32x2 helpers ----------------
__device__ __forceinline__ u64 pack2(float a, float b) {
    u64 r; asm("mov.b64 %0, {%1, %2};" : "=l"(r) : "f"(a), "f"(b)); return r;
}
__device__ __forceinline__ void fma2(u64 &d, u64 a, u64 b) {
    asm("fma.rn.f32x2 %0, %1, %2, %0;" : "+l"(d) : "l"(a), "l"(b));
}
__device__ __forceinline__ float2 unpack2(u64 v) {
    float2 r; asm("mov.b64 {%0, %1}, %2;" : "=f"(r.x), "=f"(r.y) : "l"(v)); return r;
}

// ---------------- kernel 0: transpose nn_w [256][512] -> Wt [512][256] ----------------
__global__ void k_wt(const float* __restrict__ W) {
    int idx = blockIdx.x * 256 + threadIdx.x;        // 0 .. 131071, coalesced read
    float v = W[idx];
    int o  = idx >> 9;          // row (output channel)
    int c2 = idx & 511;         // column (stacked channel)
    g_Wt[c2 * OUTC + o] = v;
}

// ---------------- kernel 1: transpose x [B][C][N] -> xT [B][N][C] ----------------
__global__ void k_transpose(const float* __restrict__ x) {
    __shared__ float tile[32][33];
    int b  = blockIdx.z;
    int n0 = blockIdx.x * 32, c0 = blockIdx.y * 32;
    int tx = threadIdx.x, ty = threadIdx.y;
    const float* xb = x + (size_t)b * CC * NN;
#pragma unroll
    for (int i = 0; i < 4; i++)
        tile[ty + i * 8][tx] = xb[(size_t)(c0 + ty + i * 8) * NN + n0 + tx];
    __syncthreads();
    float* xTb = g_xT + (size_t)b * NN * CC;
#pragma unroll
    for (int i = 0; i < 4; i++)
        xTb[(size_t)(n0 + ty + i * 8) * CC + c0 + tx] = tile[tx][ty + i * 8];
}

// ---------------- kernel 2: p,q  (dot of each node's features with a_w halves) ----------------
__global__ void k_pq(const float* __restrict__ x, const float* __restrict__ aw) {
    __shared__ float aws[2 * CC];
    int t = threadIdx.x;
    aws[t]       = aw[t];
    aws[t + 256] = aw[t + 256];
    __syncthreads();
    int b = blockIdx.y;
    int n = blockIdx.x * 256 + t;
    const float* xb = x + (size_t)b * CC * NN + n;   // column n, stride N over c (coalesced in t)
    float p = 0.f, q = 0.f;
#pragma unroll 8
    for (int c = 0; c < CC; c++) {
        float v = xb[(size_t)c * NN];
        p = fmaf(aws[c], v, p);
        q = fmaf(aws[CC + c], v, q);
    }
    g_p[b * NN + n] = p;
    g_q[b * NN + n] = q;
}

// ---------------- kernel 3: fused attention + aggregation + GEMM + ReLU ----------------
// grid (N/NT, B), 256 threads. dyn smem: St[512][NT] + es/ws/idx0 (512 each)
__global__ void __launch_bounds__(256, 2)
k_main(const float* __restrict__ x, const int* __restrict__ ei,
       const float* __restrict__ a_b, const float* __restrict__ nn_b,
       float* __restrict__ out)
{
    extern __shared__ float sm[];
    float* St  = sm;                       // [2C][NT] stacked tile (interleaved x/agg rows)
    float* ws  = sm + 2 * CC * NT;         // [NT][K] softmax weights
    float* es  = ws + NT * KK;             // [NT][K] logits
    int*   id0 = (int*)(es + NT * KK);     // [NT][K] neighbor indices

    int t  = threadIdx.x;
    int b  = blockIdx.y;
    int n0 = blockIdx.x * NT;
    const float ab = a_b[0];
    const float* pb = g_p + b * NN;
    const float* qb = g_q + b * NN;

    // ---- Phase A: logits e = p[idx1] + q[idx0] + a_b, then softmax over K ----
    // NOTE: edge_index is int32 on the wire (JAX default x64-disabled downcasts int64).
    for (int pr = t; pr < NT * KK; pr += 256) {
        int nt = pr >> 4, k = pr & 15;
        int base = ((b * NN + (n0 + nt)) * KK) + k;
        int i0 = ei[base];                            // edge_index[0] -> x_j
        int i1 = ei[BB * NN * KK + base];             // edge_index[1] -> x_i
        id0[pr] = i0;
        es[pr]  = pb[i1] + qb[i0] + ab;
    }
    __syncthreads();
    if (t < NT) {
        float m = -1e30f;
#pragma unroll
        for (int k = 0; k < KK; k++) m = fmaxf(m, es[t * KK + k]);
        float s = 0.f;
#pragma unroll
        for (int k = 0; k < KK; k++) {
            float e = __expf(es[t * KK + k] - m);
            ws[t * KK + k] = e; s += e;
        }
        float inv = 1.0f / s;
#pragma unroll
        for (int k = 0; k < KK; k++) ws[t * KK + k] *= inv;
    }
    __syncthreads();

    // ---- Phase B1: even rows of St = center features (read x [B][C][N], coalesced in n) ----
    {
        int n4 = t & 7, cl = t >> 3;                 // 8 n-chunks x 32 c-base
        const float* xb = x + (size_t)b * CC * NN;
#pragma unroll
        for (int pp = 0; pp < 8; pp++) {
            int c = cl + pp * 32;
            float4 v = *(const float4*)(xb + (size_t)c * NN + n0 + n4 * 4);
            float* d = St + (2 * c) * NT + n4 * 4;
            d[0] = v.x; d[1] = v.y; d[2] = v.z; d[3] = v.w;
        }
    }
    // ---- Phase B2: odd rows of St = softmax-weighted neighbor aggregation (gather from xT) ----
    {
        int cs = t & 7, nl = t >> 3;                 // 8 c-slices x 32 nodes
        float4 ac[8];
#pragma unroll
        for (int pp = 0; pp < 8; pp++) ac[pp] = make_float4(0.f, 0.f, 0.f, 0.f);
        const float* xTb = g_xT + (size_t)b * NN * CC;
#pragma unroll 2
        for (int k = 0; k < KK; k++) {
            int   g = id0[nl * KK + k];
            float w = ws[nl * KK + k];
            const float4* src = (const float4*)(xTb + (size_t)g * CC) + cs;
#pragma unroll
            for (int pp = 0; pp < 8; pp++) {
                float4 v = src[pp * 8];              // c = cs*4 + pp*32 (+0..3)
                ac[pp].x = fmaf(w, v.x, ac[pp].x);
                ac[pp].y = fmaf(w, v.y, ac[pp].y);
                ac[pp].z = fmaf(w, v.z, ac[pp].z);
                ac[pp].w = fmaf(w, v.w, ac[pp].w);
            }
        }
#pragma unroll
        for (int pp = 0; pp < 8; pp++) {
            int c = cs * 4 + pp * 32;
            St[(2 * c + 1) * NT + nl] = ac[pp].x;
            St[(2 * c + 3) * NT + nl] = ac[pp].y;
            St[(2 * c + 5) * NT + nl] = ac[pp].z;
            St[(2 * c + 7) * NT + nl] = ac[pp].w;
        }
    }
    __syncthreads();

    // ---- Phase C: out[o][n0..n0+31] = relu(Wt[:, o] . St[:, n] + bias), packed f32x2 ----
    int o = t;
    u64 acc[16];
#pragma unroll
    for (int j = 0; j < 16; j++) acc[j] = 0ULL;
    const float* wcol = g_Wt + o;
#pragma unroll 2
    for (int c2 = 0; c2 < 2 * CC; c2++) {
        float wv = wcol[(size_t)c2 * OUTC];          // coalesced across warp (Wt col-major)
        u64 wp = pack2(wv, wv);
        const ulonglong2* srow = (const ulonglong2*)(St + c2 * NT);  // broadcast LDS.128
#pragma unroll
        for (int j = 0; j < 8; j++) {
            ulonglong2 sv = srow[j];
            fma2(acc[2 * j],     wp, sv.x);          // n = 4j, 4j+1
            fma2(acc[2 * j + 1], wp, sv.y);          // n = 4j+2, 4j+3
        }
    }
    float bias = nn_b[o];
    float* orow = out + ((size_t)(b * OUTC + o)) * NN + n0;
#pragma unroll
    for (int j = 0; j < 8; j++) {
        float2 a0 = unpack2(acc[2 * j]);
        float2 a1 = unpack2(acc[2 * j + 1]);
        float4 r;
        r.x = fmaxf(a0.x + bias, 0.f);
        r.y = fmaxf(a0.y + bias, 0.f);
        r.z = fmaxf(a1.x + bias, 0.f);
        r.w = fmaxf(a1.y + bias, 0.f);
        ((float4*)orow)[j] = r;
    }
}

// ---------------- launch ----------------
extern "C" void kernel_launch(void* const* d_in, const int* in_sizes, int n_in,
                              void* d_out, int out_size)
{
    const float* x    = (const float*)d_in[0];
    const int*   ei   = (const int*)d_in[1];     // int32 (JAX x64-disabled)
    const float* a_w  = (const float*)d_in[2];
    const float* a_b  = (const float*)d_in[3];
    const float* nn_w = (const float*)d_in[4];
    const float* nn_b = (const float*)d_in[5];
    float*       out  = (float*)d_out;

    const int smem_main = (2 * CC * NT + 3 * NT * KK) * 4;   // 71680 B
    cudaFuncSetAttribute(k_main, cudaFuncAttributeMaxDynamicSharedMemorySize, smem_main);

    k_wt<<<(OUTC * 2 * CC) / 256, 256>>>(nn_w);
    k_transpose<<<dim3(NN / 32, CC / 32, BB), dim3(32, 8)>>>(x);
    k_pq<<<dim3(NN / 256, BB), 256>>>(x, a_w);
    k_main<<<dim3(NN / NT, BB), 256, smem_main>>>(x, ei, a_b, nn_b, out);
}

// round 14
// speedup vs baseline: 2.8346x; 2.8346x over previous
#include <cuda_runtime.h>
#include <cstdint>

#define BB   8
#define CC   256
#define NN   2048
#define KK   16
#define OUTC 256
#define O2   512        // stacked output rows: [0,256)=Z (even cols of nn_w), [256,512)=Y (odd)
#define MT   128        // node tile (MMA M)
#define KC   32         // K chunk: 32 floats = 128 B = one SW128 atom row

// tcgen05 only exists on arch-specific targets (sm_100a/101a/103a). Guard so the
// compute_103 (no-'a') ptxas pass compiles a scalar fallback instead of dying.
#if defined(__CUDA_ARCH_FEAT_SM103_ALL) || defined(__CUDA_ARCH_FEAT_SM100_ALL) || defined(__CUDA_ARCH_FEAT_SM101_ALL)
#define GA_TCGEN05 1
#else
#define GA_TCGEN05 0
#endif

typedef unsigned long long u64;

// ---------------- scratch ----------------
__device__ float g_MW [O2 * CC];          // [o2][c], K-major, tf32-rounded (tcgen05 B operand)
__device__ float g_WtT[CC * O2];          // [c][o2] transposed weights (fallback GEMM operand)
__device__ float g_p  [BB * NN];
__device__ float g_q  [BB * NN];
__device__ float g_Y2T[(size_t)BB * NN * O2];  // [b][n][o2]: cols 0..255=Z, 256..511=Y

// ---------------- generic helpers ----------------
__device__ __forceinline__ uint32_t smem_u32(const void* p) {
    uint32_t a; asm("{ .reg .u64 t; cvta.to.shared.u64 t, %1; cvt.u32.u64 %0, t; }" : "=r"(a) : "l"(p));
    return a;
}
__device__ __forceinline__ uint32_t elect1() {
    uint32_t p; asm volatile("{ .reg .pred p; elect.sync _|p, 0xFFFFFFFF; selp.b32 %0, 1, 0, p; }" : "=r"(p));
    return p;
}
__device__ __forceinline__ float to_tf32(float f) {
    uint32_t u; asm("cvt.rna.tf32.f32 %0, %1;" : "=r"(u) : "f"(f));
    return __uint_as_float(u);
}
__device__ __forceinline__ void sts4(uint32_t a, float4 v) {
    asm volatile("st.shared.v4.f32 [%0], {%1,%2,%3,%4};" :: "r"(a), "f"(v.x), "f"(v.y), "f"(v.z), "f"(v.w));
}
__device__ __forceinline__ u64 pack2(float a, float b) {
    u64 r; asm("mov.b64 %0, {%1, %2};" : "=l"(r) : "f"(a), "f"(b)); return r;
}
__device__ __forceinline__ void fma2(u64 &d, u64 a, u64 b) {
    asm("fma.rn.f32x2 %0, %1, %2, %0;" : "+l"(d) : "l"(a), "l"(b));
}
__device__ __forceinline__ float2 unpack2(u64 v) {
    float2 r; asm("mov.b64 {%0, %1}, %2;" : "=f"(r.x), "=f"(r.y) : "l"(v)); return r;
}
#define SWZ(x) ((x) ^ (((x) >> 3) & 0x70))

#if GA_TCGEN05
#define TCGEN05_ALLOC(sm, n)  asm volatile("tcgen05.alloc.cta_group::1.sync.aligned.shared::cta.b32 [%0], %1;" :: "r"(sm), "r"(n) : "memory")
#define TCGEN05_DEALLOC(t, n) asm volatile("tcgen05.dealloc.cta_group::1.sync.aligned.b32 %0, %1;" :: "r"(t), "r"(n))
#define TCGEN05_RELINQ()      asm volatile("tcgen05.relinquish_alloc_permit.cta_group::1.sync.aligned;")
#define TCGEN05_COMMIT(mb)    asm volatile("tcgen05.commit.cta_group::1.mbarrier::arrive::one.shared::cluster.b64 [%0];" :: "r"(mb) : "memory")
#define TCGEN05_WAIT_LD()     asm volatile("tcgen05.wait::ld.sync.aligned;" ::: "memory")
#define TCGEN05_FENCE_AFTER()  asm volatile("tcgen05.fence::after_thread_sync;" ::: "memory")
#define TCGEN05_FENCE_BEFORE() asm volatile("tcgen05.fence::before_thread_sync;" ::: "memory")
#define MBAR_INIT(mb, c)      asm volatile("mbarrier.init.shared.b64 [%0], %1;" :: "r"(mb), "r"(c) : "memory")

#define MBAR_WAIT(mb, par) do {                                                  \
    uint32_t _m = (mb), _p = (par), _d;                                          \
    asm volatile("{ .reg .pred p; mbarrier.try_wait.parity.acquire.cta.shared::cta.b64 p, [%1], %2; selp.b32 %0,1,0,p; }" \
                 : "=r"(_d) : "r"(_m), "r"(_p) : "memory");                      \
    if (!_d) {                                                                   \
        asm volatile("{ .reg .pred P1; WL%=: mbarrier.try_wait.parity.acquire.cta.shared::cta.b64 P1, [%0], %1, 0x989680; @P1 bra.uni WD%=; bra.uni WL%=; WD%=: }" \
                     :: "r"(_m), "r"(_p) : "memory");                            \
    }                                                                            \
} while (0)

#define TCGEN05_LD_X32(r, ta)                                                    \
    asm volatile("tcgen05.ld.sync.aligned.32x32b.x32.b32 "                       \
        "{%0,%1,%2,%3,%4,%5,%6,%7,%8,%9,%10,%11,%12,%13,%14,%15,"                \
        "%16,%17,%18,%19,%20,%21,%22,%23,%24,%25,%26,%27,%28,%29,%30,%31}, [%32];" \
        : "=r"((r)[0]),"=r"((r)[1]),"=r"((r)[2]),"=r"((r)[3]),"=r"((r)[4]),"=r"((r)[5]),"=r"((r)[6]),"=r"((r)[7]), \
          "=r"((r)[8]),"=r"((r)[9]),"=r"((r)[10]),"=r"((r)[11]),"=r"((r)[12]),"=r"((r)[13]),"=r"((r)[14]),"=r"((r)[15]), \
          "=r"((r)[16]),"=r"((r)[17]),"=r"((r)[18]),"=r"((r)[19]),"=r"((r)[20]),"=r"((r)[21]),"=r"((r)[22]),"=r"((r)[23]), \
          "=r"((r)[24]),"=r"((r)[25]),"=r"((r)[26]),"=r"((r)[27]),"=r"((r)[28]),"=r"((r)[29]),"=r"((r)[30]),"=r"((r)[31]) \
        : "r"(ta))

static __device__ __forceinline__ uint64_t make_desc(uint32_t addr) {
    // SW128, Blackwell v1, LBO=1, SBO=64 (8-row x 128B atoms, contiguous)
    const uint64_t base = (uint64_t(2) << 61) | (uint64_t(1) << 46) | (uint64_t(64) << 32) | (uint64_t(1) << 16);
    return base | ((uint64_t)(addr >> 4) & 0x3FFF);
}
// idesc: d=f32(1<<4), a=tf32(2<<7), b=tf32(2<<10), N=128(16<<17), M=128(8<<24)
#define IDESC_TF32 ((1u << 4) | (2u << 7) | (2u << 10) | (16u << 17) | (8u << 24))

__device__ __forceinline__ void mma_tf32_ss(uint32_t d, uint64_t ad, uint64_t bd, uint32_t idesc, bool en) {
    uint32_t e = en ? 1u : 0u;
    asm volatile("{ .reg .pred p; setp.ne.u32 p, %5, 0;\n\t"
                 "tcgen05.mma.cta_group::1.kind::tf32 [%0], %1, %2, %3, {%4,%4,%4,%4}, p; }"
                 :: "r"(d), "l"(ad), "l"(bd), "r"(idesc), "r"(0u), "r"(e) : "memory");
}
#endif  // GA_TCGEN05

// ---------------- k_mw: MW[o2][c] (tcgen05 B) + WtT[c][o2] (fallback), tf32-rounded ----------------
__global__ void k_mw(const float* __restrict__ W) {
    int idx = blockIdx.x * 256 + threadIdx.x;     // 0..131071, coalesced read of nn_w
    float v = to_tf32(W[idx]);
    int o = idx >> 9, j = idx & 511;
    int c = j >> 1, half = j & 1;
    int o2 = half * 256 + o;
    g_MW [o2 * CC + c]  = v;
    g_WtT[c  * O2 + o2] = v;
}

// ---------------- k_pq ----------------
__global__ void k_pq(const float* __restrict__ x, const float* __restrict__ aw) {
    __shared__ float aws[2 * CC];
    int t = threadIdx.x;
    aws[t] = aw[t]; aws[t + 256] = aw[t + 256];
    __syncthreads();
    int b = blockIdx.y;
    int n = blockIdx.x * 256 + t;
    const float* xb = x + (size_t)b * CC * NN + n;
    float p = 0.f, q = 0.f;
#pragma unroll 8
    for (int c = 0; c < CC; c++) {
        float v = xb[(size_t)c * NN];
        p = fmaf(aws[c], v, p);
        q = fmaf(aws[CC + c], v, q);
    }
    g_p[b * NN + n] = p;
    g_q[b * NN + n] = q;
}

// ---------------- k_gemm: Y2T[b][n][o2] = (MW @ xs)^T ----------------
#define SM_A(buf)  ((buf) * 16384)
#define SM_B(buf)  (32768 + (buf) * 65536)
#define SM_CTRL    163840
#define SM_MBAR0   (SM_CTRL + 16)
#define SM_MBAR1   (SM_CTRL + 24)
#define SM_TOTAL   (SM_CTRL + 64 + 1024)

__global__ void __launch_bounds__(256, 1)
k_gemm(const float* __restrict__ x) {
    extern __shared__ char smraw[];
    int t = threadIdx.x;
    int b = blockIdx.y, n0 = blockIdx.x * MT;
    const float* xb = x + (size_t)b * CC * NN;

#if GA_TCGEN05
    uint32_t sb = (smem_u32(smraw) + 1023) & ~1023u;
    int wid = t >> 5, lid = t & 31;

    if (wid == 0) TCGEN05_ALLOC(sb + SM_CTRL, 512);
    if (t == 0) { MBAR_INIT(sb + SM_MBAR0, 1); MBAR_INIT(sb + SM_MBAR1, 1); }
    __syncthreads();
    uint32_t tmem;
    asm volatile("ld.shared.b32 %0, [%1];" : "=r"(tmem) : "r"(sb + SM_CTRL));

    for (int kc = 0; kc < 8; kc++) {
        int buf = kc & 1;
        if (kc >= 2) MBAR_WAIT(sb + SM_MBAR0 + 8 * buf, ((kc >> 1) + 1) & 1);  // MMA(kc-2) done

        // A tile: smemA[node][c] <- x[c][n0+node]; coalesced LDG, conflict-free STS.128
        {
            int nl = t & 127, ch = t >> 7;           // node row, c-half (16 channels)
            const float* src = xb + (size_t)(kc * KC + ch * 16) * NN + n0 + nl;
            float v[16];
#pragma unroll
            for (int c = 0; c < 16; c++) v[c] = to_tf32(src[(size_t)c * NN]);
            uint32_t ab = sb + SM_A(buf);
#pragma unroll
            for (int jj = 0; jj < 4; jj++)
                sts4(ab + SWZ(nl * 128 + ch * 64 + jj * 16),
                     make_float4(v[jj * 4], v[jj * 4 + 1], v[jj * 4 + 2], v[jj * 4 + 3]));
        }
        // B tile: smemB[o2][c] <- g_MW rows (already tf32), straight copy + swizzle
        {
            int rg = t >> 3, j8 = t & 7;
            uint32_t bb = sb + SM_B(buf);
#pragma unroll
            for (int i = 0; i < 16; i++) {
                int r = rg + i * 32;
                float4 v = *(const float4*)(g_MW + (size_t)r * CC + kc * KC + j8 * 4);
                sts4(bb + SWZ(r * 128 + j8 * 16), v);
            }
        }
        asm volatile("fence.proxy.async.shared::cta;" ::: "memory");
        __syncthreads();

        if (wid == 0 && elect1()) {
            uint64_t ad = make_desc(sb + SM_A(buf));
#pragma unroll
            for (int q = 0; q < 4; q++) {                 // 4 N-quadrants of 128 o2-rows
                uint64_t bd = make_desc(sb + SM_B(buf) + q * 16384);
#pragma unroll
                for (int s = 0; s < 4; s++)               // 4 K-steps of 8 (K=32 chunk)
                    mma_tf32_ss(tmem + q * 128, ad + s * 2, bd + s * 2, IDESC_TF32, !(kc == 0 && s == 0));
            }
            TCGEN05_COMMIT(sb + SM_MBAR0 + 8 * buf);
        }
    }
    MBAR_WAIT(sb + SM_MBAR0, 1);   // commit #4 on each buffer -> parity 1
    MBAR_WAIT(sb + SM_MBAR1, 1);
    TCGEN05_FENCE_AFTER();

    // store D: warp (sub=wid&3) owns nodes sub*32+lid; col half by wid>>2
    int sub = wid & 3;
    int node = n0 + sub * 32 + lid;
    int ch = (wid >> 2) * 256;
    float* dst0 = g_Y2T + ((size_t)b * NN + node) * O2 + ch;
#pragma unroll
    for (int cb = 0; cb < 8; cb++) {
        uint32_t r[32];
        TCGEN05_LD_X32(r, tmem + ch + cb * 32);
        TCGEN05_WAIT_LD();
        float4* dst = (float4*)(dst0 + cb * 32);
#pragma unroll
        for (int j = 0; j < 8; j++)
            dst[j] = make_float4(__uint_as_float(r[4 * j]), __uint_as_float(r[4 * j + 1]),
                                 __uint_as_float(r[4 * j + 2]), __uint_as_float(r[4 * j + 3]));
    }
    TCGEN05_FENCE_BEFORE();
    __syncthreads();
    if (wid == 0) { TCGEN05_RELINQ(); TCGEN05_DEALLOC(tmem, 512); }

#else  // ---- fallback: f32x2 FFMA GEMM (no tcgen05 on this ptxas target) ----
    float* As = (float*)smraw;                     // [256 c][128 node] = 128 KB
    for (int i = t; i < CC * MT; i += 256)         // i = c*128 + node; coalesced LDG+STS
        As[i] = xb[(size_t)(i >> 7) * NN + n0 + (i & 127)];
    __syncthreads();

    int slot = t & 63, ng = t >> 6;                // o2-pair slot, 32-node group
    for (int p = 0; p < 4; p++) {
        int o2p = p * 64 + slot;                   // o2 pair index (o2 = 2*o2p, 2*o2p+1)
        u64 acc0[16], acc1[16];
#pragma unroll
        for (int j = 0; j < 16; j++) { acc0[j] = 0ULL; acc1[j] = 0ULL; }
        const float2* wp = (const float2*)g_WtT + o2p;      // row c at +c*256 (float2 units)
#pragma unroll 2
        for (int c = 0; c < CC; c++) {
            float2 w = wp[c * (O2 / 2)];
            u64 w0 = pack2(w.x, w.x), w1 = pack2(w.y, w.y);
            const ulonglong2* av = (const ulonglong2*)(As + c * 128 + ng * 32);  // broadcast LDS.128
#pragma unroll
            for (int j = 0; j < 8; j++) {
                ulonglong2 a = av[j];
                fma2(acc0[2 * j],     w0, a.x); fma2(acc0[2 * j + 1], w0, a.y);
                fma2(acc1[2 * j],     w1, a.x); fma2(acc1[2 * j + 1], w1, a.y);
            }
        }
        float* outr = g_Y2T + ((size_t)b * NN + n0 + ng * 32) * O2 + 2 * o2p;
#pragma unroll
        for (int j = 0; j < 16; j++) {
            float2 a0 = unpack2(acc0[j]);          // nodes 2j, 2j+1 @ o2 even
            float2 a1 = unpack2(acc1[j]);          // nodes 2j, 2j+1 @ o2 odd
            *(float2*)(outr + (size_t)(2 * j) * O2)     = make_float2(a0.x, a1.x);
            *(float2*)(outr + (size_t)(2 * j + 1) * O2) = make_float2(a0.y, a1.y);
        }
    }
#endif
}

// ---------------- k_att: softmax + gather of Y + add Z + bias + relu + transpose-out ----------------
__global__ void __launch_bounds__(256)
k_att(const int* __restrict__ ei, const float* __restrict__ a_b,
      const float* __restrict__ nn_b, float* __restrict__ out) {
    __shared__ float ws[32 * KK], es[32 * KK];
    __shared__ int   id0[32 * KK];
    __shared__ float bias[OUTC];
    __shared__ float St[OUTC * 33];

    int t = threadIdx.x, b = blockIdx.y, n0 = blockIdx.x * 32;
    bias[t] = nn_b[t];
    const float ab = a_b[0];
    const float* pb = g_p + b * NN;
    const float* qb = g_q + b * NN;

    // logits
    for (int pr = t; pr < 32 * KK; pr += 256) {
        int nt = pr >> 4, k = pr & 15;
        int base = ((b * NN + (n0 + nt)) * KK) + k;
        int i0 = ei[base];
        int i1 = ei[BB * NN * KK + base];
        id0[pr] = i0;
        es[pr]  = pb[i1] + qb[i0] + ab;
    }
    __syncthreads();
    if (t < 32) {
        float m = -1e30f;
#pragma unroll
        for (int k = 0; k < KK; k++) m = fmaxf(m, es[t * KK + k]);
        float s = 0.f;
#pragma unroll
        for (int k = 0; k < KK; k++) { float e = __expf(es[t * KK + k] - m); ws[t * KK + k] = e; s += e; }
        float inv = 1.0f / s;
#pragma unroll
        for (int k = 0; k < KK; k++) ws[t * KK + k] *= inv;
    }
    __syncthreads();

    // gather Y (cols 256..511 of Y2T rows), weighted sum over K
    int nl = t >> 3, cs = t & 7;
    float4 acc[8];
#pragma unroll
    for (int pp = 0; pp < 8; pp++) acc[pp] = make_float4(0.f, 0.f, 0.f, 0.f);
    const float* ybase = g_Y2T + (size_t)b * NN * O2;
#pragma unroll 2
    for (int k = 0; k < KK; k++) {
        int   g = id0[nl * KK + k];
        float w = ws[nl * KK + k];
        const float4* src = (const float4*)(ybase + (size_t)g * O2 + 256) + cs;
#pragma unroll
        for (int pp = 0; pp < 8; pp++) {
            float4 v = src[pp * 8];
            acc[pp].x = fmaf(w, v.x, acc[pp].x);
            acc[pp].y = fmaf(w, v.y, acc[pp].y);
            acc[pp].z = fmaf(w, v.z, acc[pp].z);
            acc[pp].w = fmaf(w, v.w, acc[pp].w);
        }
    }
    // add Z (cols 0..255 of this node's row) + bias, relu, stage transposed
    const float4* zr = (const float4*)(ybase + (size_t)(n0 + nl) * O2) + cs;
#pragma unroll
    for (int pp = 0; pp < 8; pp++) {
        float4 z = zr[pp * 8];
        int c0 = (cs + pp * 8) * 4;
        St[(c0 + 0) * 33 + nl] = fmaxf(z.x + acc[pp].x + bias[c0 + 0], 0.f);
        St[(c0 + 1) * 33 + nl] = fmaxf(z.y + acc[pp].y + bias[c0 + 1], 0.f);
        St[(c0 + 2) * 33 + nl] = fmaxf(z.z + acc[pp].z + bias[c0 + 2], 0.f);
        St[(c0 + 3) * 33 + nl] = fmaxf(z.w + acc[pp].w + bias[c0 + 3], 0.f);
    }
    __syncthreads();

    // write out[b][o][n0..n0+31], o = t
    int o = t;
    float* orow = out + ((size_t)(b * OUTC + o)) * NN + n0;
#pragma unroll
    for (int j = 0; j < 8; j++) {
        float4 r;
        r.x = St[o * 33 + j * 4 + 0];
        r.y = St[o * 33 + j * 4 + 1];
        r.z = St[o * 33 + j * 4 + 2];
        r.w = St[o * 33 + j * 4 + 3];
        ((float4*)orow)[j] = r;
    }
}

// ---------------- launch ----------------
extern "C" void kernel_launch(void* const* d_in, const int* in_sizes, int n_in,
                              void* d_out, int out_size)
{
    const float* x    = (const float*)d_in[0];
    const int*   ei   = (const int*)d_in[1];     // int32 on the wire
    const float* a_w  = (const float*)d_in[2];
    const float* a_b  = (const float*)d_in[3];
    const float* nn_w = (const float*)d_in[4];
    const float* nn_b = (const float*)d_in[5];
    float*       out  = (float*)d_out;

    cudaFuncSetAttribute(k_gemm, cudaFuncAttributeMaxDynamicSharedMemorySize, SM_TOTAL);

    k_mw  <<<(O2 * CC) / 256, 256>>>(nn_w);
    k_pq  <<<dim3(NN / 256, BB), 256>>>(x, a_w);
    k_gemm<<<dim3(NN / MT, BB), 256, SM_TOTAL>>>(x);
    k_att <<<dim3(NN / 32, BB), 256>>>(ei, a_b, nn_b, out);
}

// round 16
// speedup vs baseline: 3.0055x; 1.0603x over previous
#include <cuda_runtime.h>
#include <cstdint>

#define BB   8
#define CC   256
#define NN   2048
#define KK   16
#define OUTC 256
#define O2   512        // stacked output rows: [0,256)=Z (even cols of nn_w), [256,512)=Y (odd)
#define MT   128        // node tile (MMA M)
#define KC   32         // K chunk: 32 floats = 128 B = one SW128 atom row

// tcgen05 only exists on arch-specific targets (sm_100a/101a/103a). Guard so the
// compute_103 (no-'a') ptxas pass compiles a scalar fallback instead of dying.
#if defined(__CUDA_ARCH_FEAT_SM103_ALL) || defined(__CUDA_ARCH_FEAT_SM100_ALL) || defined(__CUDA_ARCH_FEAT_SM101_ALL)
#define GA_TCGEN05 1
#else
#define GA_TCGEN05 0
#endif

typedef unsigned long long u64;

// ---------------- scratch ----------------
__device__ float g_MW [O2 * CC];          // [o2][c], K-major, tf32-rounded (tcgen05 B operand)
__device__ float g_WtT[CC * O2];          // [c][o2] transposed weights (fallback GEMM operand, full fp32)
__device__ float g_p  [BB * NN];
__device__ float g_q  [BB * NN];
__device__ float g_Y2T[(size_t)BB * NN * O2];  // [b][n][o2]: cols 0..255=Z, 256..511=Y

// ---------------- generic helpers ----------------
__device__ __forceinline__ uint32_t smem_u32(const void* p) {
    uint32_t a; asm("{ .reg .u64 t; cvta.to.shared.u64 t, %1; cvt.u32.u64 %0, t; }" : "=r"(a) : "l"(p));
    return a;
}
__device__ __forceinline__ uint32_t elect1() {
    uint32_t p; asm volatile("{ .reg .pred p; elect.sync _|p, 0xFFFFFFFF; selp.b32 %0, 1, 0, p; }" : "=r"(p));
    return p;
}
__device__ __forceinline__ float to_tf32(float f) {
    uint32_t u; asm("cvt.rna.tf32.f32 %0, %1;" : "=r"(u) : "f"(f));
    return __uint_as_float(u);
}
__device__ __forceinline__ void sts4(uint32_t a, float4 v) {
    asm volatile("st.shared.v4.f32 [%0], {%1,%2,%3,%4};" :: "r"(a), "f"(v.x), "f"(v.y), "f"(v.z), "f"(v.w));
}
__device__ __forceinline__ u64 pack2(float a, float b) {
    u64 r; asm("mov.b64 %0, {%1, %2};" : "=l"(r) : "f"(a), "f"(b)); return r;
}
__device__ __forceinline__ void fma2(u64 &d, u64 a, u64 b) {
    asm("fma.rn.f32x2 %0, %1, %2, %0;" : "+l"(d) : "l"(a), "l"(b));
}
__device__ __forceinline__ float2 unpack2(u64 v) {
    float2 r; asm("mov.b64 {%0, %1}, %2;" : "=f"(r.x), "=f"(r.y) : "l"(v)); return r;
}
#define SWZ(x) ((x) ^ (((x) >> 3) & 0x70))

#if GA_TCGEN05
#define TCGEN05_ALLOC(sm, n)  asm volatile("tcgen05.alloc.cta_group::1.sync.aligned.shared::cta.b32 [%0], %1;" :: "r"(sm), "r"(n) : "memory")
#define TCGEN05_DEALLOC(t, n) asm volatile("tcgen05.dealloc.cta_group::1.sync.aligned.b32 %0, %1;" :: "r"(t), "r"(n))
#define TCGEN05_RELINQ()      asm volatile("tcgen05.relinquish_alloc_permit.cta_group::1.sync.aligned;")
#define TCGEN05_COMMIT(mb)    asm volatile("tcgen05.commit.cta_group::1.mbarrier::arrive::one.shared::cluster.b64 [%0];" :: "r"(mb) : "memory")
#define TCGEN05_WAIT_LD()     asm volatile("tcgen05.wait::ld.sync.aligned;" ::: "memory")
#define TCGEN05_FENCE_AFTER()  asm volatile("tcgen05.fence::after_thread_sync;" ::: "memory")
#define TCGEN05_FENCE_BEFORE() asm volatile("tcgen05.fence::before_thread_sync;" ::: "memory")
#define MBAR_INIT(mb, c)      asm volatile("mbarrier.init.shared.b64 [%0], %1;" :: "r"(mb), "r"(c) : "memory")

#define MBAR_WAIT(mb, par) do {                                                  \
    uint32_t _m = (mb), _p = (par), _d;                                          \
    asm volatile("{ .reg .pred p; mbarrier.try_wait.parity.acquire.cta.shared::cta.b64 p, [%1], %2; selp.b32 %0,1,0,p; }" \
                 : "=r"(_d) : "r"(_m), "r"(_p) : "memory");                      \
    if (!_d) {                                                                   \
        asm volatile("{ .reg .pred P1; WL%=: mbarrier.try_wait.parity.acquire.cta.shared::cta.b64 P1, [%0], %1, 0x989680; @P1 bra.uni WD%=; bra.uni WL%=; WD%=: }" \
                     :: "r"(_m), "r"(_p) : "memory");                            \
    }                                                                            \
} while (0)

#define TCGEN05_LD_X32(r, ta)                                                    \
    asm volatile("tcgen05.ld.sync.aligned.32x32b.x32.b32 "                       \
        "{%0,%1,%2,%3,%4,%5,%6,%7,%8,%9,%10,%11,%12,%13,%14,%15,"                \
        "%16,%17,%18,%19,%20,%21,%22,%23,%24,%25,%26,%27,%28,%29,%30,%31}, [%32];" \
        : "=r"((r)[0]),"=r"((r)[1]),"=r"((r)[2]),"=r"((r)[3]),"=r"((r)[4]),"=r"((r)[5]),"=r"((r)[6]),"=r"((r)[7]), \
          "=r"((r)[8]),"=r"((r)[9]),"=r"((r)[10]),"=r"((r)[11]),"=r"((r)[12]),"=r"((r)[13]),"=r"((r)[14]),"=r"((r)[15]), \
          "=r"((r)[16]),"=r"((r)[17]),"=r"((r)[18]),"=r"((r)[19]),"=r"((r)[20]),"=r"((r)[21]),"=r"((r)[22]),"=r"((r)[23]), \
          "=r"((r)[24]),"=r"((r)[25]),"=r"((r)[26]),"=r"((r)[27]),"=r"((r)[28]),"=r"((r)[29]),"=r"((r)[30]),"=r"((r)[31]) \
        : "r"(ta))

static __device__ __forceinline__ uint64_t make_desc(uint32_t addr) {
    // SW128, Blackwell v1, LBO=1, SBO=64 (8-row x 128B atoms, contiguous)
    const uint64_t base = (uint64_t(2) << 61) | (uint64_t(1) << 46) | (uint64_t(64) << 32) | (uint64_t(1) << 16);
    return base | ((uint64_t)(addr >> 4) & 0x3FFF);
}
// idesc: d=f32(1<<4), a=tf32(2<<7), b=tf32(2<<10), N=128(16<<17), M=128(8<<24)
#define IDESC_TF32 ((1u << 4) | (2u << 7) | (2u << 10) | (16u << 17) | (8u << 24))

__device__ __forceinline__ void mma_tf32_ss(uint32_t d, uint64_t ad, uint64_t bd, uint32_t idesc, bool en) {
    uint32_t e = en ? 1u : 0u;
    asm volatile("{ .reg .pred p; setp.ne.u32 p, %5, 0;\n\t"
                 "tcgen05.mma.cta_group::1.kind::tf32 [%0], %1, %2, %3, {%4,%4,%4,%4}, p; }"
                 :: "r"(d), "l"(ad), "l"(bd), "r"(idesc), "r"(0u), "r"(e) : "memory");
}
#endif  // GA_TCGEN05

// ---------------- k_mw: MW[o2][c] (tcgen05 B, tf32) + WtT[c][o2] (fallback, fp32) ----------------
__global__ void k_mw(const float* __restrict__ W) {
    int idx = blockIdx.x * 256 + threadIdx.x;     // 0..131071, coalesced read of nn_w
    float v = W[idx];
    int o = idx >> 9, j = idx & 511;
    int c = j >> 1, half = j & 1;
    int o2 = half * 256 + o;
    g_MW [o2 * CC + c]  = to_tf32(v);
    g_WtT[c  * O2 + o2] = v;
}

// ---------------- k_pq ----------------
__global__ void k_pq(const float* __restrict__ x, const float* __restrict__ aw) {
    __shared__ float aws[2 * CC];
    int t = threadIdx.x;
    aws[t] = aw[t]; aws[t + 256] = aw[t + 256];
    __syncthreads();
    int b = blockIdx.y;
    int n = blockIdx.x * 256 + t;
    const float* xb = x + (size_t)b * CC * NN + n;
    float p = 0.f, q = 0.f;
#pragma unroll 8
    for (int c = 0; c < CC; c++) {
        float v = xb[(size_t)c * NN];
        p = fmaf(aws[c], v, p);
        q = fmaf(aws[CC + c], v, q);
    }
    g_p[b * NN + n] = p;
    g_q[b * NN + n] = q;
}

// ---------------- k_gemm: Y2T[b][n][o2] = (MW @ xs)^T ----------------
#define SM_A(buf)  ((buf) * 16384)
#define SM_B(buf)  (32768 + (buf) * 65536)
#define SM_CTRL    163840
#define SM_MBAR0   (SM_CTRL + 16)
#define SM_MBAR1   (SM_CTRL + 24)
#define SM_TOTAL   (SM_CTRL + 64 + 1024)

__global__ void __launch_bounds__(256, 1)
k_gemm(const float* __restrict__ x) {
    extern __shared__ char smraw[];
    int t = threadIdx.x;
    int b = blockIdx.y, n0 = blockIdx.x * MT;
    const float* xb = x + (size_t)b * CC * NN;

#if GA_TCGEN05
    uint32_t sb = (smem_u32(smraw) + 1023) & ~1023u;
    int wid = t >> 5, lid = t & 31;

    if (wid == 0) TCGEN05_ALLOC(sb + SM_CTRL, 512);
    if (t == 0) { MBAR_INIT(sb + SM_MBAR0, 1); MBAR_INIT(sb + SM_MBAR1, 1); }
    __syncthreads();
    uint32_t tmem;
    asm volatile("ld.shared.b32 %0, [%1];" : "=r"(tmem) : "r"(sb + SM_CTRL));

    for (int kc = 0; kc < 8; kc++) {
        int buf = kc & 1;
        if (kc >= 2) MBAR_WAIT(sb + SM_MBAR0 + 8 * buf, ((kc >> 1) + 1) & 1);  // MMA(kc-2) done

        // A tile: smemA[node][c] <- x[c][n0+node]; coalesced LDG, conflict-free STS.128
        {
            int nl = t & 127, ch = t >> 7;           // node row, c-half (16 channels)
            const float* src = xb + (size_t)(kc * KC + ch * 16) * NN + n0 + nl;
            float v[16];
#pragma unroll
            for (int c = 0; c < 16; c++) v[c] = to_tf32(src[(size_t)c * NN]);
            uint32_t ab = sb + SM_A(buf);
#pragma unroll
            for (int jj = 0; jj < 4; jj++)
                sts4(ab + SWZ(nl * 128 + ch * 64 + jj * 16),
                     make_float4(v[jj * 4], v[jj * 4 + 1], v[jj * 4 + 2], v[jj * 4 + 3]));
        }
        // B tile: smemB[o2][c] <- g_MW rows (already tf32), straight copy + swizzle
        {
            int rg = t >> 3, j8 = t & 7;
            uint32_t bb = sb + SM_B(buf);
#pragma unroll
            for (int i = 0; i < 16; i++) {
                int r = rg + i * 32;
                float4 v = *(const float4*)(g_MW + (size_t)r * CC + kc * KC + j8 * 4);
                sts4(bb + SWZ(r * 128 + j8 * 16), v);
            }
        }
        asm volatile("fence.proxy.async.shared::cta;" ::: "memory");
        __syncthreads();

        if (wid == 0 && elect1()) {
            uint64_t ad = make_desc(sb + SM_A(buf));
#pragma unroll
            for (int q = 0; q < 4; q++) {                 // 4 N-quadrants of 128 o2-rows
                uint64_t bd = make_desc(sb + SM_B(buf) + q * 16384);
#pragma unroll
                for (int s = 0; s < 4; s++)               // 4 K-steps of 8 (K=32 chunk)
                    mma_tf32_ss(tmem + q * 128, ad + s * 2, bd + s * 2, IDESC_TF32, !(kc == 0 && s == 0));
            }
            TCGEN05_COMMIT(sb + SM_MBAR0 + 8 * buf);
        }
    }
    MBAR_WAIT(sb + SM_MBAR0, 1);   // commit #4 on each buffer -> parity 1
    MBAR_WAIT(sb + SM_MBAR1, 1);
    TCGEN05_FENCE_AFTER();

    // store D: warp (sub=wid&3) owns nodes sub*32+lid; col half by wid>>2
    int sub = wid & 3;
    int node = n0 + sub * 32 + lid;
    int ch = (wid >> 2) * 256;
    float* dst0 = g_Y2T + ((size_t)b * NN + node) * O2 + ch;
#pragma unroll
    for (int cb = 0; cb < 8; cb++) {
        uint32_t r[32];
        TCGEN05_LD_X32(r, tmem + ch + cb * 32);
        TCGEN05_WAIT_LD();
        float4* dst = (float4*)(dst0 + cb * 32);
#pragma unroll
        for (int j = 0; j < 8; j++)
            dst[j] = make_float4(__uint_as_float(r[4 * j]), __uint_as_float(r[4 * j + 1]),
                                 __uint_as_float(r[4 * j + 2]), __uint_as_float(r[4 * j + 3]));
    }
    TCGEN05_FENCE_BEFORE();
    __syncthreads();
    if (wid == 0) { TCGEN05_RELINQ(); TCGEN05_DEALLOC(tmem, 512); }

#else  // ---- fallback: f32x2 FFMA GEMM (no tcgen05 on this ptxas target) ----
    float* As = (float*)smraw;                     // [256 c][128 node] = 128 KB
    for (int i = t; i < CC * MT; i += 256)         // i = c*128 + node; coalesced LDG+STS
        As[i] = xb[(size_t)(i >> 7) * NN + n0 + (i & 127)];
    __syncthreads();

    int slot = t & 63, ng = t >> 6;                // o2-pair slot, 32-node group
    for (int p = 0; p < 4; p++) {
        int o2p = p * 64 + slot;                   // o2 pair index (o2 = 2*o2p, 2*o2p+1)
        u64 acc0[16], acc1[16];
#pragma unroll
        for (int j = 0; j < 16; j++) { acc0[j] = 0ULL; acc1[j] = 0ULL; }
        const float2* wp = (const float2*)g_WtT + o2p;      // row c at +c*256 (float2 units)
#pragma unroll 2
        for (int c = 0; c < CC; c++) {
            float2 w = wp[c * (O2 / 2)];
            u64 w0 = pack2(w.x, w.x), w1 = pack2(w.y, w.y);
            const ulonglong2* av = (const ulonglong2*)(As + c * 128 + ng * 32);  // broadcast LDS.128
#pragma unroll
            for (int j = 0; j < 8; j++) {
                ulonglong2 a = av[j];
                fma2(acc0[2 * j],     w0, a.x); fma2(acc0[2 * j + 1], w0, a.y);
                fma2(acc1[2 * j],     w1, a.x); fma2(acc1[2 * j + 1], w1, a.y);
            }
        }
        float* outr = g_Y2T + ((size_t)b * NN + n0 + ng * 32) * O2 + 2 * o2p;
#pragma unroll
        for (int j = 0; j < 16; j++) {
            float2 a0 = unpack2(acc0[j]);          // nodes 2j, 2j+1 @ o2 even
            float2 a1 = unpack2(acc1[j]);          // nodes 2j, 2j+1 @ o2 odd
            *(float2*)(outr + (size_t)(2 * j) * O2)     = make_float2(a0.x, a1.x);
            *(float2*)(outr + (size_t)(2 * j + 1) * O2) = make_float2(a0.y, a1.y);
        }
    }
#endif
}

// ---------------- k_att: softmax + gather of Y + add Z + bias + relu + transpose-out ----------------
// grid (N/32, B, 2): blockIdx.z selects a 128-channel half. Smaller per-thread state
// (acc[4] vs acc[8]) -> ~5 blocks/SM instead of 3 -> 2x warps to hide gather latency.
#define CH 128
__global__ void __launch_bounds__(256)
k_att(const int* __restrict__ ei, const float* __restrict__ a_b,
      const float* __restrict__ nn_b, float* __restrict__ out) {
    __shared__ float ws[32 * KK], es[32 * KK];
    __shared__ int   id0[32 * KK];
    __shared__ float bias[CH];
    __shared__ float St[CH * 33];

    int t = threadIdx.x, b = blockIdx.y, n0 = blockIdx.x * 32;
    int ch0 = blockIdx.z * CH;
    if (t < CH) bias[t] = nn_b[ch0 + t];
    const float ab = a_b[0];
    const float* pb = g_p + b * NN;
    const float* qb = g_q + b * NN;

    // logits (recomputed per z-half; 512 values, trivial)
    for (int pr = t; pr < 32 * KK; pr += 256) {
        int nt = pr >> 4, k = pr & 15;
        int base = ((b * NN + (n0 + nt)) * KK) + k;
        int i0 = ei[base];
        int i1 = ei[BB * NN * KK + base];
        id0[pr] = i0;
        es[pr]  = pb[i1] + qb[i0] + ab;
    }
    __syncthreads();
    if (t < 32) {
        float m = -1e30f;
#pragma unroll
        for (int k = 0; k < KK; k++) m = fmaxf(m, es[t * KK + k]);
        float s = 0.f;
#pragma unroll
        for (int k = 0; k < KK; k++) { float e = __expf(es[t * KK + k] - m); ws[t * KK + k] = e; s += e; }
        float inv = 1.0f / s;
#pragma unroll
        for (int k = 0; k < KK; k++) ws[t * KK + k] *= inv;
    }
    __syncthreads();

    // gather this half's Y channels (cols 256+ch0 .. 256+ch0+127), weighted sum over K
    int nl = t >> 3, cs = t & 7;                   // node 0..31, float4 slice 0..7
    float4 acc[4];
#pragma unroll
    for (int pp = 0; pp < 4; pp++) acc[pp] = make_float4(0.f, 0.f, 0.f, 0.f);
    const float* ybase = g_Y2T + (size_t)b * NN * O2;
#pragma unroll 4
    for (int k = 0; k < KK; k++) {
        int   g = id0[nl * KK + k];
        float w = ws[nl * KK + k];
        const float4* src = (const float4*)(ybase + (size_t)g * O2 + 256 + ch0) + cs;
#pragma unroll
        for (int pp = 0; pp < 4; pp++) {
            float4 v = src[pp * 8];                // local channel float4 index cs + pp*8
            acc[pp].x = fmaf(w, v.x, acc[pp].x);
            acc[pp].y = fmaf(w, v.y, acc[pp].y);
            acc[pp].z = fmaf(w, v.z, acc[pp].z);
            acc[pp].w = fmaf(w, v.w, acc[pp].w);
        }
    }
    // add Z (this half's cols of this node's row) + bias, relu, stage transposed
    const float4* zr = (const float4*)(ybase + (size_t)(n0 + nl) * O2 + ch0) + cs;
#pragma unroll
    for (int pp = 0; pp < 4; pp++) {
        float4 z = zr[pp * 8];
        int c0 = (cs + pp * 8) * 4;                // local channel 0..127
        St[(c0 + 0) * 33 + nl] = fmaxf(z.x + acc[pp].x + bias[c0 + 0], 0.f);
        St[(c0 + 1) * 33 + nl] = fmaxf(z.y + acc[pp].y + bias[c0 + 1], 0.f);
        St[(c0 + 2) * 33 + nl] = fmaxf(z.z + acc[pp].z + bias[c0 + 2], 0.f);
        St[(c0 + 3) * 33 + nl] = fmaxf(z.w + acc[pp].w + bias[c0 + 3], 0.f);
    }
    __syncthreads();

    // write out[b][ch0+ol][n0 + half*16 .. +16); 256 threads = 128 channels x 2 node-halves
    int ol = t >> 1, half = t & 1;
    float* orow = out + ((size_t)(b * OUTC + ch0 + ol)) * NN + n0 + half * 16;
    const float* sr = St + ol * 33 + half * 16;
#pragma unroll
    for (int j = 0; j < 4; j++)
        ((float4*)orow)[j] = make_float4(sr[j * 4 + 0], sr[j * 4 + 1], sr[j * 4 + 2], sr[j * 4 + 3]);
}

// ---------------- launch ----------------
extern "C" void kernel_launch(void* const* d_in, const int* in_sizes, int n_in,
                              void* d_out, int out_size)
{
    const float* x    = (const float*)d_in[0];
    const int*   ei   = (const int*)d_in[1];     // int32 on the wire
    const float* a_w  = (const float*)d_in[2];
    const float* a_b  = (const float*)d_in[3];
    const float* nn_w = (const float*)d_in[4];
    const float* nn_b = (const float*)d_in[5];
    float*       out  = (float*)d_out;

    cudaFuncSetAttribute(k_gemm, cudaFuncAttributeMaxDynamicSharedMemorySize, SM_TOTAL);

    k_mw  <<<(O2 * CC) / 256, 256>>>(nn_w);
    k_pq  <<<dim3(NN / 256, BB), 256>>>(x, a_w);
    k_gemm<<<dim3(NN / MT, BB), 256, SM_TOTAL>>>(x);
    k_att <<<dim3(NN / 32, BB, 2), 256>>>(ei, a_b, nn_b, out);
}